// round 1
// baseline (speedup 1.0000x reference)
#include <cuda_runtime.h>

// Potential_6347961663538 — Gaussian form-factor splatting onto a 128x128 grid.
//
// out[b,i,j] = sum_a sum_f (ff_a*4π/ff_b)[a,f] * exp(-π*(4π/ff_b)[a,f] *
//              ((j-64 - c0[b,a])^2 + (i-64 - c1[b,a])^2))
//
// Since π*invb >= 4π²/2 ≈ 19.74, any term with per-axis |d| > 3.5 underflows
// fp32 exp to exactly 0 (exp(-242)), identical to what the reference adds.
// So a 7x7 window around round(coord) reproduces every nonzero fp32 term.
// The exponential is separable: exp(-k(dx²+dy²)) = exp(-k dx²)*exp(-k dy²),
// so each atom needs only 5*7 + 5*7 = 70 exps instead of 5*49.

#define SIDELEN 128
#define NATOM   2048
#define NB      4
#define NF      5
#define RAD     3
#define WIN     7          // 2*RAD+1
#define PI_F    3.14159265358979323846f

__global__ void zero_out_kernel(float* __restrict__ out, int n) {
    int i = blockIdx.x * blockDim.x + threadIdx.x;
    if (i < n) out[i] = 0.0f;
}

__global__ void __launch_bounds__(96) potential_scatter_kernel(
    const float* __restrict__ coords,   // [NB, NATOM, 3]
    const float* __restrict__ ff_a,     // [NATOM, NF]
    const float* __restrict__ ff_b,     // [NATOM, NF]
    float* __restrict__ out)            // [NB, SIDELEN, SIDELEN]
{
    const int atom = blockIdx.x;        // b*NATOM + a
    const int b = atom >> 11;
    const int a = atom & (NATOM - 1);

    const float c0 = coords[atom * 3 + 0];   // maps to j (fast axis)
    const float c1 = coords[atom * 3 + 1];   // maps to i (slow axis)
    const int jc = __float2int_rn(c0) + SIDELEN / 2;
    const int ic = __float2int_rn(c1) + SIDELEN / 2;

    // Whole window outside the grid -> nothing to do (block-uniform branch).
    if (jc + RAD < 0 || jc - RAD >= SIDELEN || ic + RAD < 0 || ic - RAD >= SIDELEN)
        return;

    __shared__ float s_ex[NF][WIN];
    __shared__ float s_ey[NF][WIN];
    __shared__ float s_coef[NF];

    const int t = threadIdx.x;

    // 70 threads: build the separable exp tables.
    if (t < NF * 2 * WIN) {
        const int f = t / (2 * WIN);
        const int r = t % (2 * WIN);
        const float fb  = ff_b[a * NF + f];
        const float pib = (4.0f * PI_F * PI_F) / fb;   // π * invb
        if (r < WIN) {
            const float dx = (float)(jc - SIDELEN / 2 - RAD + r) - c0;
            s_ex[f][r] = __expf(-pib * dx * dx);
        } else {
            const int rr = r - WIN;
            const float dy = (float)(ic - SIDELEN / 2 - RAD + rr) - c1;
            s_ey[f][rr] = __expf(-pib * dy * dy);
        }
    }
    // 5 threads: coefficients coef = ff_a * invb.
    if (t < NF) {
        s_coef[t] = ff_a[a * NF + t] * (4.0f * PI_F) / ff_b[a * NF + t];
    }
    __syncthreads();

    // 49 threads: one window pixel each.
    if (t < WIN * WIN) {
        const int wi = t / WIN;
        const int wj = t % WIN;
        const int i = ic - RAD + wi;
        const int j = jc - RAD + wj;
        if ((unsigned)i < SIDELEN && (unsigned)j < SIDELEN) {
            float s = 0.0f;
            #pragma unroll
            for (int f = 0; f < NF; f++)
                s = fmaf(s_coef[f] * s_ex[f][wj], s_ey[f][wi], s);
            if (s != 0.0f)
                atomicAdd(&out[(b * SIDELEN + i) * SIDELEN + j], s);
        }
    }
}

extern "C" void kernel_launch(void* const* d_in, const int* in_sizes, int n_in,
                              void* d_out, int out_size) {
    const float* coords = (const float*)d_in[0];
    const float* ff_a   = (const float*)d_in[1];
    const float* ff_b   = (const float*)d_in[2];
    float* out = (float*)d_out;

    zero_out_kernel<<<(out_size + 1023) / 1024, 1024>>>(out, out_size);
    potential_scatter_kernel<<<NB * NATOM, 96>>>(coords, ff_a, ff_b, out);
}

// round 2
// speedup vs baseline: 1.2294x; 1.2294x over previous
#include <cuda_runtime.h>

// Potential_6347961663538 — Gaussian form-factor splatting onto a 128x128 grid.
//
// out[b,i,j] = sum_a sum_f (ff_a*4π/ff_b)[a,f] *
//              exp(-π*(4π/ff_b)[a,f] * ((j-64-c0[b,a])^2 + (i-64-c1[b,a])^2))
//
// π*invb = 4π²/ff_b >= 19.74, so any term with per-axis |d| > 3.5 underflows
// fp32 exp to exactly 0 — identical to the zeros the reference adds. A 7x7
// window around round(coord) therefore reproduces every nonzero fp32 term.
// The exponential is separable, so each atom needs 70 exps, not 245.
//
// R2: one WARP per atom (was one 96-thread block). No __syncthreads, no dead
// warps, coef folded into the x-table. 1024 blocks x 256 threads.

#define SIDELEN 128
#define NATOM   2048
#define NB      4
#define NF      5
#define RAD     3
#define WIN     7
#define WPB     8            // warps per block

__global__ void zero_out_kernel(float* __restrict__ out, int n) {
    int i = blockIdx.x * blockDim.x + threadIdx.x;
    if (i < n) out[i] = 0.0f;
}

__global__ void __launch_bounds__(WPB * 32) potential_scatter_kernel(
    const float* __restrict__ coords,   // [NB, NATOM, 3]
    const float* __restrict__ ff_a,     // [NATOM, NF]
    const float* __restrict__ ff_b,     // [NATOM, NF]
    float* __restrict__ out)            // [NB, SIDELEN, SIDELEN]
{
    const int warp = blockIdx.x * WPB + (threadIdx.x >> 5);  // = b*NATOM + a
    const int lane = threadIdx.x & 31;
    const int b = warp >> 11;
    const int a = warp & (NATOM - 1);

    const float c0 = coords[warp * 3 + 0];   // maps to j (fast axis)
    const float c1 = coords[warp * 3 + 1];   // maps to i (slow axis)
    const int jc = __float2int_rn(c0);       // window center in grid-centered coords
    const int ic = __float2int_rn(c1);

    // tab[0..34]  = coef[f] * exp(-pib*dx_r^2)   (f*7 + r)
    // tab[35..69] = exp(-pib*dy_r^2)
    __shared__ float s_tab[WPB][72];
    float* t = s_tab[threadIdx.x >> 5];

    #pragma unroll
    for (int idx = lane; idx < NF * 2 * WIN; idx += 32) {
        const bool isx = idx < NF * WIN;
        const int  k   = isx ? idx : idx - NF * WIN;
        const int  f   = k / WIN;
        const int  r   = k - f * WIN;
        const float inv = __fdividef(1.0f, ff_b[a * NF + f]);
        const float pib = 39.4784176f * inv;            // 4*pi^2 / ff_b
        if (isx) {
            const float dx   = (float)(jc - RAD + r) - c0;
            const float coef = ff_a[a * NF + f] * 12.5663706f * inv;  // ff_a*4pi/ff_b
            t[idx] = coef * __expf(-pib * dx * dx);
        } else {
            const float dy = (float)(ic - RAD + r) - c1;
            t[idx] = __expf(-pib * dy * dy);
        }
    }
    __syncwarp();

    const int jbase = jc + SIDELEN / 2 - RAD;
    const int ibase = ic + SIDELEN / 2 - RAD;

    #pragma unroll
    for (int p = lane; p < WIN * WIN; p += 32) {
        const int wi = p / WIN;
        const int wj = p - wi * WIN;
        const int i = ibase + wi;
        const int j = jbase + wj;
        if ((unsigned)i < SIDELEN && (unsigned)j < SIDELEN) {
            float s = t[wj] * t[NF * WIN + wi];
            #pragma unroll
            for (int f = 1; f < NF; f++)
                s = fmaf(t[f * WIN + wj], t[NF * WIN + f * WIN + wi], s);
            if (s != 0.0f)
                atomicAdd(&out[(b << 14) + (i << 7) + j], s);
        }
    }
}

extern "C" void kernel_launch(void* const* d_in, const int* in_sizes, int n_in,
                              void* d_out, int out_size) {
    const float* coords = (const float*)d_in[0];
    const float* ff_a   = (const float*)d_in[1];
    const float* ff_b   = (const float*)d_in[2];
    float* out = (float*)d_out;

    zero_out_kernel<<<(out_size + 255) / 256, 256>>>(out, out_size);
    potential_scatter_kernel<<<(NB * NATOM) / WPB, WPB * 32>>>(coords, ff_a, ff_b, out);
}

// round 3
// speedup vs baseline: 1.2657x; 1.0295x over previous
#include <cuda_runtime.h>

// Potential_6347961663538 — Gaussian form-factor splatting onto a 128x128 grid.
//
// out[b,i,j] = sum_a sum_f (ff_a*4π/ff_b)[a,f] *
//              exp(-π*(4π/ff_b)[a,f] * ((j-64-c0[b,a])^2 + (i-64-c1[b,a])^2))
//
// π*invb = 4π²/ff_b >= 19.74, so any term with per-axis |d| > 3.5 underflows
// fp32 exp to exactly 0 — identical to the zeros the reference adds. A 7x7
// window around round(coord) reproduces every nonzero fp32 term. The
// exponential is separable: 70 exps per atom instead of 245.
//
// R3: table layout transposed to [axis][r][f] (f contiguous, padded to 8)
// so each pixel reads its 5 x-terms and 5 y-terms with LDS.128+LDS.32
// (4 LDS/pixel instead of 10). Zero-init via graph memset node instead of
// a kernel node.

#define SIDELEN 128
#define NATOM   2048
#define NB      4
#define NF      5
#define RAD     3
#define WIN     7
#define WPB     8            // warps per block

__global__ void __launch_bounds__(WPB * 32) potential_scatter_kernel(
    const float* __restrict__ coords,   // [NB, NATOM, 3]
    const float* __restrict__ ff_a,     // [NATOM, NF]
    const float* __restrict__ ff_b,     // [NATOM, NF]
    float* __restrict__ out)            // [NB, SIDELEN, SIDELEN]
{
    const int warp = blockIdx.x * WPB + (threadIdx.x >> 5);  // = b*NATOM + a
    const int lane = threadIdx.x & 31;
    const int b = warp >> 11;
    const int a = warp & (NATOM - 1);

    const float c0 = coords[warp * 3 + 0];   // maps to j (fast axis)
    const float c1 = coords[warp * 3 + 1];   // maps to i (slow axis)
    const int jc = __float2int_rn(c0);       // window center, grid-centered coords
    const int ic = __float2int_rn(c1);

    // t[0][r][f] = coef[f] * exp(-pib[f]*dx_r^2)   (x axis, coef folded in)
    // t[1][r][f] = exp(-pib[f]*dy_r^2)             (y axis)
    // f padded to 8 floats -> &t[ax][r][0] is 32B aligned (float4-able).
    __shared__ float s_tab[WPB][2][WIN][8];
    float (*t)[WIN][8] = s_tab[threadIdx.x >> 5];

    // 70 jobs: k = r*5+f per axis.
    #pragma unroll
    for (int idx = lane; idx < 2 * WIN * NF; idx += 32) {
        const int  axis = (idx >= WIN * NF);
        const int  k    = idx - axis * (WIN * NF);
        const int  r    = k / NF;
        const int  f    = k - r * NF;
        const float inv = __fdividef(1.0f, ff_b[a * NF + f]);
        const float pib = 39.4784176f * inv;             // 4*pi^2 / ff_b
        if (axis == 0) {
            const float dx   = (float)(jc - RAD + r) - c0;
            const float coef = ff_a[a * NF + f] * 12.5663706f * inv;  // ff_a*4pi/ff_b
            t[0][r][f] = coef * __expf(-pib * dx * dx);
        } else {
            const float dy = (float)(ic - RAD + r) - c1;
            t[1][r][f] = __expf(-pib * dy * dy);
        }
    }
    __syncwarp();

    const int jbase = jc + SIDELEN / 2 - RAD;
    const int ibase = ic + SIDELEN / 2 - RAD;

    #pragma unroll
    for (int p = lane; p < WIN * WIN; p += 32) {
        const int wi = p / WIN;
        const int wj = p - wi * WIN;
        const int i = ibase + wi;
        const int j = jbase + wj;
        if ((unsigned)i < SIDELEN && (unsigned)j < SIDELEN) {
            const float4 x4 = *(const float4*)&t[0][wj][0];
            const float  x5 = t[0][wj][4];
            const float4 y4 = *(const float4*)&t[1][wi][0];
            const float  y5 = t[1][wi][4];
            float s = x4.x * y4.x;
            s = fmaf(x4.y, y4.y, s);
            s = fmaf(x4.z, y4.z, s);
            s = fmaf(x4.w, y4.w, s);
            s = fmaf(x5,   y5,   s);
            if (s != 0.0f)
                atomicAdd(&out[(b << 14) + (i << 7) + j], s);
        }
    }
}

extern "C" void kernel_launch(void* const* d_in, const int* in_sizes, int n_in,
                              void* d_out, int out_size) {
    const float* coords = (const float*)d_in[0];
    const float* ff_a   = (const float*)d_in[1];
    const float* ff_b   = (const float*)d_in[2];
    float* out = (float*)d_out;

    cudaMemsetAsync(out, 0, (size_t)out_size * sizeof(float));
    potential_scatter_kernel<<<(NB * NATOM) / WPB, WPB * 32>>>(coords, ff_a, ff_b, out);
}